// round 5
// baseline (speedup 1.0000x reference)
#include <cuda_runtime.h>
#include <math.h>
#include <stdint.h>

#define BATCH 4096
#define HID   1024
#define NOUT  4096   // 4*H

// Scratch (graph-capture safe static device globals)
__device__ float g_ifgo[(size_t)BATCH * NOUT];
__device__ float g_hr [(size_t)BATCH * HID];    // k-pair-interleaved tf32
__device__ float g_xr [(size_t)BATCH * HID];
__device__ float g_Whp[(size_t)HID * NOUT];     // packed [k/8][n][8] tf32
__device__ float g_Wxp[(size_t)HID * NOUT];

// perm within 8-block: [0,4,1,5,2,6,3,7] -> pos(k) = ((k&3)<<1) | ((k&4)>>2)
__device__ __forceinline__ int kperm8(int k) { return ((k & 3) << 1) | ((k & 4) >> 2); }

// ---------------------------------------------------------------------------
// Prepass 1: h/x -> tf32(RNA), k-pair interleaved within each 8-block.
// ---------------------------------------------------------------------------
__global__ void cvt_hx_kernel(const float* __restrict__ s0, float* __restrict__ d0,
                              const float* __restrict__ s1, float* __restrict__ d1, int n)
{
    int stride = gridDim.x * blockDim.x;
    for (int i = blockIdx.x * blockDim.x + threadIdx.x; i < n; i += stride) {
        int k  = i & (HID - 1);
        int di = (i & ~(HID - 1)) | (k & ~7) | kperm8(k & 7);
        uint32_t u;
        asm("cvt.rna.tf32.f32 %0, %1;" : "=r"(u) : "f"(s0[i])); d0[di] = __uint_as_float(u);
        asm("cvt.rna.tf32.f32 %0, %1;" : "=r"(u) : "f"(s1[i])); d1[di] = __uint_as_float(u);
    }
}

// ---------------------------------------------------------------------------
// Prepass 2: W [1024 k][4096 n] -> Wp [(k/8)][n][perm(k%8)], tf32(RNA).
// Block handles 8k x 128n; reads and writes fully coalesced.
// ---------------------------------------------------------------------------
__global__ __launch_bounds__(256) void pack_w_kernel(
    const float* __restrict__ W, float* __restrict__ Wp)
{
    __shared__ float t[128 * 8];
    const int bn = blockIdx.x * 128;
    const int bk = blockIdx.y * 8;
    const int tid = threadIdx.x;
    #pragma unroll
    for (int e = tid; e < 1024; e += 256) {
        int kk = e >> 7;        // 0..7
        int n  = e & 127;
        float v = W[(size_t)(bk + kk) * NOUT + bn + n];
        uint32_t u; asm("cvt.rna.tf32.f32 %0, %1;" : "=r"(u) : "f"(v));
        t[n * 8 + kperm8(kk)] = __uint_as_float(u);
    }
    __syncthreads();
    float* dst = Wp + ((size_t)blockIdx.y * NOUT + bn) * 8;
    #pragma unroll
    for (int e = tid; e < 1024; e += 256) dst[e] = t[e];
}

// ---------------------------------------------------------------------------
// tf32 mma.sync GEMM: ifgo = h @ W_h + x @ W_x + b_h
// CTA 128x128, 4 warps (2x2 of 64x64), BK=16, 4-stage cp.async ring,
// one __syncthreads per tile, all fragment loads are LDS.64.
// ---------------------------------------------------------------------------
#define BM 128
#define BN 128
#define BK 16
#define ASTR 20          // A row stride (floats); rows are 16 floats + 4 pad
#define STAGES 4
#define NKTILES 128      // 2 passes * (1024/16)
#define A_STG_FLT (BM * ASTR)      // 2560 floats = 10240 B
#define B_STG_FLT (BK * BN)        // 2048 floats =  8192 B
#define GEMM_SMEM ((A_STG_FLT + B_STG_FLT) * STAGES * 4)   // 73728 B

__device__ __forceinline__ void cpa16(uint32_t dst, const float* src) {
    asm volatile("cp.async.cg.shared.global [%0], [%1], 16;\n" :: "r"(dst), "l"(src));
}
__device__ __forceinline__ void cpa_commit() {
    asm volatile("cp.async.commit_group;\n" ::: "memory");
}
__device__ __forceinline__ void cpa_wait2() {
    asm volatile("cp.async.wait_group 2;\n" ::: "memory");
}

__global__ __launch_bounds__(128, 2) void gemm_tf32_kernel(const float* __restrict__ b_h)
{
    extern __shared__ float smem[];
    float* As = smem;                              // STAGES x A_STG_FLT
    float* Bs = smem + STAGES * A_STG_FLT;         // STAGES x B_STG_FLT

    const int tid  = threadIdx.x;
    const int lane = tid & 31;
    const int wid  = tid >> 5;         // 0..3
    const int wm   = wid >> 1;         // 0..1 -> 64 rows
    const int wn   = wid & 1;          // 0..1 -> 64 cols
    const int qid  = lane >> 2;        // 0..7
    const int cid  = lane & 3;         // 0..3

    const int brow = blockIdx.y * BM;
    const int bcol = blockIdx.x * BN;

    const float* Aops[2] = { g_hr, g_xr };
    const float* Wops[2] = { g_Whp, g_Wxp };

    const uint32_t as_u = (uint32_t)__cvta_generic_to_shared(As);
    const uint32_t bs_u = (uint32_t)__cvta_generic_to_shared(Bs);

    // A staging: thread = one row, 4 x 16B (16 floats = two whole 8-blocks)
    // B staging: thread tid: group = tid>>6 (0/1), chunk = tid&63, 4 x 16B
    const int b_grp = tid >> 6;
    const int b_idx = tid & 63;

    auto stage = [&](int t, int buf) {
        const int pass = t >> 6;
        const int kloc = (t & 63);             // k-tile within pass
        const float* A = Aops[pass];
        const float* W = Wops[pass];
        // A: rows brow..brow+127, k [kloc*16, +16)
        const float* asrc = A + (size_t)(brow + tid) * HID + kloc * 16;
        uint32_t adst = as_u + (uint32_t)(buf * A_STG_FLT + tid * ASTR) * 4u;
        #pragma unroll
        for (int c = 0; c < 4; ++c) cpa16(adst + c * 16u, asrc + c * 4);
        // B: two groups g = kloc*2 + b_grp, columns bcol..bcol+127 contiguous
        const float* bsrc = W + ((size_t)(kloc * 2 + b_grp) * NOUT + bcol) * 8 + b_idx * 16;
        uint32_t bdst = bs_u + (uint32_t)(buf * B_STG_FLT + b_grp * 1024 + b_idx * 16) * 4u;
        #pragma unroll
        for (int c = 0; c < 4; ++c) cpa16(bdst + c * 16u, bsrc + c * 4);
        cpa_commit();
    };

    float acc[4][8][4];
    #pragma unroll
    for (int i = 0; i < 4; ++i)
        #pragma unroll
        for (int j = 0; j < 8; ++j)
            #pragma unroll
            for (int r = 0; r < 4; ++r) acc[i][j][r] = 0.f;

    stage(0, 0); stage(1, 1); stage(2, 2);

    #pragma unroll 1
    for (int t = 0; t < NKTILES; ++t) {
        const int buf = t & (STAGES - 1);
        cpa_wait2();
        __syncthreads();
        if (t + 3 < NKTILES) stage(t + 3, (t + 3) & (STAGES - 1));

        const float* a0 = As + buf * A_STG_FLT;
        const float* b0 = Bs + buf * B_STG_FLT;

        #pragma unroll
        for (int ks = 0; ks < BK; ks += 8) {
            float2 afr[4][2];
            #pragma unroll
            for (int i = 0; i < 4; ++i) {
                int m = wm * 64 + i * 16 + qid;
                afr[i][0] = *(const float2*)&a0[(m    ) * ASTR + ks + 2 * cid];
                afr[i][1] = *(const float2*)&a0[(m + 8) * ASTR + ks + 2 * cid];
            }
            #pragma unroll
            for (int j = 0; j < 8; ++j) {
                int n = wn * 64 + j * 8 + qid;
                float2 bfr = *(const float2*)&b0[((ks >> 3) * BN + n) * 8 + 2 * cid];
                uint32_t bx = __float_as_uint(bfr.x), by = __float_as_uint(bfr.y);
                #pragma unroll
                for (int i = 0; i < 4; ++i) {
                    asm volatile(
                        "mma.sync.aligned.m16n8k8.row.col.f32.tf32.tf32.f32 "
                        "{%0,%1,%2,%3}, {%4,%5,%6,%7}, {%8,%9}, {%0,%1,%2,%3};\n"
                        : "+f"(acc[i][j][0]), "+f"(acc[i][j][1]),
                          "+f"(acc[i][j][2]), "+f"(acc[i][j][3])
                        : "r"(__float_as_uint(afr[i][0].x)), "r"(__float_as_uint(afr[i][1].x)),
                          "r"(__float_as_uint(afr[i][0].y)), "r"(__float_as_uint(afr[i][1].y)),
                          "r"(bx), "r"(by));
                }
            }
        }
    }

    // Epilogue: bias + store
    #pragma unroll
    for (int i = 0; i < 4; ++i) {
        int r0 = brow + wm * 64 + i * 16 + qid;
        #pragma unroll
        for (int j = 0; j < 8; ++j) {
            int col = bcol + wn * 64 + j * 8 + 2 * cid;
            float2 bb = *(const float2*)&b_h[col];
            float2 v0 = { acc[i][j][0] + bb.x, acc[i][j][1] + bb.y };
            float2 v1 = { acc[i][j][2] + bb.x, acc[i][j][3] + bb.y };
            *(float2*)&g_ifgo[(size_t)r0       * NOUT + col] = v0;
            *(float2*)&g_ifgo[(size_t)(r0 + 8) * NOUT + col] = v1;
        }
    }
}

// ---------------------------------------------------------------------------
// Kernel 2: per-row LayerNorm(4 gates) + LSTM pointwise + LayerNorm(c_next)
// ---------------------------------------------------------------------------
__device__ __forceinline__ void warpReduce2(float& a, float& b) {
    #pragma unroll
    for (int o = 16; o > 0; o >>= 1) {
        a += __shfl_down_sync(0xffffffffu, a, o);
        b += __shfl_down_sync(0xffffffffu, b, o);
    }
}
__device__ __forceinline__ float sigmoidf_(float v) { return 1.0f / (1.0f + expf(-v)); }

__global__ __launch_bounds__(256) void ln_lstm_kernel(
    const float* __restrict__ c,
    const float* __restrict__ ln_g, const float* __restrict__ ln_b,
    const float* __restrict__ lnc_g, const float* __restrict__ lnc_b,
    float* __restrict__ h_next, float* __restrict__ c_next_out)
{
    const int b   = blockIdx.x;
    const int tid = threadIdx.x;
    const int lane = tid & 31, warp = tid >> 5;
    const float* __restrict__ row = &g_ifgo[(size_t)b * NOUT];

    __shared__ float s_wa[8], s_wb[8];
    __shared__ float s_mean[4], s_rstd[4];
    __shared__ float s_c[HID];
    __shared__ float s_o[HID];
    __shared__ float s_cmu, s_crstd;

    #pragma unroll 1
    for (int g = 0; g < 4; ++g) {
        float sum = 0.f, sq = 0.f;
        #pragma unroll
        for (int j = tid; j < HID; j += 256) {
            float v = row[g * HID + j];
            sum += v; sq += v * v;
        }
        warpReduce2(sum, sq);
        if (lane == 0) { s_wa[warp] = sum; s_wb[warp] = sq; }
        __syncthreads();
        if (warp == 0) {
            float a2 = (lane < 8) ? s_wa[lane] : 0.f;
            float b2 = (lane < 8) ? s_wb[lane] : 0.f;
            warpReduce2(a2, b2);
            if (lane == 0) {
                float mu  = a2 * (1.0f / HID);
                float var = b2 * (1.0f / HID) - mu * mu;
                s_mean[g] = mu;
                s_rstd[g] = rsqrtf(var + 1e-5f);
            }
        }
        __syncthreads();
    }

    const float mu_i = s_mean[0], rs_i = s_rstd[0];
    const float mu_f = s_mean[1], rs_f = s_rstd[1];
    const float mu_g = s_mean[2], rs_g = s_rstd[2];
    const float mu_o = s_mean[3], rs_o = s_rstd[3];

    float csum = 0.f, csq = 0.f;
    #pragma unroll
    for (int j = tid; j < HID; j += 256) {
        float iv = (row[0 * HID + j] - mu_i) * rs_i * ln_g[0 * HID + j] + ln_b[0 * HID + j];
        float fv = (row[1 * HID + j] - mu_f) * rs_f * ln_g[1 * HID + j] + ln_b[1 * HID + j];
        float gv = (row[2 * HID + j] - mu_g) * rs_g * ln_g[2 * HID + j] + ln_b[2 * HID + j];
        float ov = (row[3 * HID + j] - mu_o) * rs_o * ln_g[3 * HID + j] + ln_b[3 * HID + j];

        float cn = sigmoidf_(fv) * c[(size_t)b * HID + j] + sigmoidf_(iv) * tanhf(gv);
        s_c[j] = cn;
        s_o[j] = ov;
        c_next_out[(size_t)b * HID + j] = cn;
        csum += cn; csq += cn * cn;
    }

    warpReduce2(csum, csq);
    if (lane == 0) { s_wa[warp] = csum; s_wb[warp] = csq; }
    __syncthreads();
    if (warp == 0) {
        float a2 = (lane < 8) ? s_wa[lane] : 0.f;
        float b2 = (lane < 8) ? s_wb[lane] : 0.f;
        warpReduce2(a2, b2);
        if (lane == 0) {
            float mu  = a2 * (1.0f / HID);
            float var = b2 * (1.0f / HID) - mu * mu;
            s_cmu = mu;
            s_crstd = rsqrtf(var + 1e-5f);
        }
    }
    __syncthreads();

    const float cmu = s_cmu, crstd = s_crstd;
    #pragma unroll
    for (int j = tid; j < HID; j += 256) {
        float lnc = (s_c[j] - cmu) * crstd * lnc_g[j] + lnc_b[j];
        h_next[(size_t)b * HID + j] = sigmoidf_(s_o[j]) * tanhf(lnc);
    }
}

// ---------------------------------------------------------------------------
extern "C" void kernel_launch(void* const* d_in, const int* in_sizes, int n_in,
                              void* d_out, int out_size)
{
    const float* x     = (const float*)d_in[0];
    const float* h     = (const float*)d_in[1];
    const float* c     = (const float*)d_in[2];
    const float* W_h   = (const float*)d_in[3];
    const float* b_h   = (const float*)d_in[4];
    const float* W_x   = (const float*)d_in[5];
    const float* ln_g  = (const float*)d_in[6];
    const float* ln_b  = (const float*)d_in[7];
    const float* lnc_g = (const float*)d_in[8];
    const float* lnc_b = (const float*)d_in[9];

    float* out    = (float*)d_out;
    float* h_next = out;
    float* c_next = out + (size_t)BATCH * HID;

    float *d_hr, *d_xr, *d_Whp, *d_Wxp;
    cudaGetSymbolAddress((void**)&d_hr,  g_hr);
    cudaGetSymbolAddress((void**)&d_xr,  g_xr);
    cudaGetSymbolAddress((void**)&d_Whp, g_Whp);
    cudaGetSymbolAddress((void**)&d_Wxp, g_Wxp);

    cvt_hx_kernel<<<1024, 256>>>(h, d_hr, x, d_xr, BATCH * HID);
    dim3 pgrid(NOUT / 128, HID / 8);
    pack_w_kernel<<<pgrid, 256>>>(W_h, d_Whp);
    pack_w_kernel<<<pgrid, 256>>>(W_x, d_Wxp);

    cudaFuncSetAttribute(gemm_tf32_kernel,
                         cudaFuncAttributeMaxDynamicSharedMemorySize, GEMM_SMEM);
    dim3 grid(NOUT / BN, BATCH / BM);
    gemm_tf32_kernel<<<grid, 128, GEMM_SMEM>>>(b_h);

    ln_lstm_kernel<<<BATCH, 256>>>(c, ln_g, ln_b, lnc_g, lnc_b, h_next, c_next);
}

// round 6
// speedup vs baseline: 1.6425x; 1.6425x over previous
#include <cuda_runtime.h>
#include <math.h>
#include <stdint.h>

#define BATCH 4096
#define HID   1024
#define NOUT  4096   // 4*H

// Scratch (graph-capture safe static device globals)
__device__ float g_ifgo[(size_t)BATCH * NOUT];
__device__ float g_hr [(size_t)BATCH * HID];    // tf32-rounded, row-major
__device__ float g_xr [(size_t)BATCH * HID];
__device__ float g_Whp[(size_t)HID * NOUT];     // packed [k/4][n][4] tf32
__device__ float g_Wxp[(size_t)HID * NOUT];

// ---------------------------------------------------------------------------
// Prepass 1: h/x -> tf32(RNA), plain row-major.
// ---------------------------------------------------------------------------
__global__ void cvt_hx_kernel(const float* __restrict__ s0, float* __restrict__ d0,
                              const float* __restrict__ s1, float* __restrict__ d1, int n)
{
    int stride = gridDim.x * blockDim.x;
    for (int i = blockIdx.x * blockDim.x + threadIdx.x; i < n; i += stride) {
        uint32_t u;
        asm("cvt.rna.tf32.f32 %0, %1;" : "=r"(u) : "f"(s0[i])); d0[i] = __uint_as_float(u);
        asm("cvt.rna.tf32.f32 %0, %1;" : "=r"(u) : "f"(s1[i])); d1[i] = __uint_as_float(u);
    }
}

// ---------------------------------------------------------------------------
// Prepass 2: W [1024 k][4096 n] -> Wp [k/4][n][k%4], tf32(RNA).
// Reads coalesced across n; writes float4 coalesced.
// ---------------------------------------------------------------------------
__global__ __launch_bounds__(256) void pack_w_kernel(
    const float* __restrict__ W, float* __restrict__ Wp)
{
    const int n  = blockIdx.x * 256 + threadIdx.x;
    const int k4 = blockIdx.y;
    float4 v;
    uint32_t u;
    asm("cvt.rna.tf32.f32 %0, %1;" : "=r"(u) : "f"(W[(size_t)(k4 * 4 + 0) * NOUT + n])); v.x = __uint_as_float(u);
    asm("cvt.rna.tf32.f32 %0, %1;" : "=r"(u) : "f"(W[(size_t)(k4 * 4 + 1) * NOUT + n])); v.y = __uint_as_float(u);
    asm("cvt.rna.tf32.f32 %0, %1;" : "=r"(u) : "f"(W[(size_t)(k4 * 4 + 2) * NOUT + n])); v.z = __uint_as_float(u);
    asm("cvt.rna.tf32.f32 %0, %1;" : "=r"(u) : "f"(W[(size_t)(k4 * 4 + 3) * NOUT + n])); v.w = __uint_as_float(u);
    *(float4*)&Wp[((size_t)k4 * NOUT + n) * 4] = v;
}

// ---------------------------------------------------------------------------
// tf32 mma.sync GEMM: ifgo = h @ W_h + x @ W_x + b_h
// CTA 128x128, 8 warps (4x2 of 32x64), BK=16, 4-stage cp.async ring,
// ldmatrix.x4 fragment loads, one __syncthreads per tile.
// ---------------------------------------------------------------------------
#define BM 128
#define BN 128
#define BK 16
#define ASTR 20                    // A smem row stride (floats)
#define STAGES 4
#define NKTILES 128                // 2 passes * (1024/16)
#define A_STG_FLT (BM * ASTR)      // 2560 floats = 10240 B
#define B_STG_FLT (BK * BN)        // 2048 floats =  8192 B
#define GEMM_SMEM ((A_STG_FLT + B_STG_FLT) * STAGES * 4)   // 73728 B

__device__ __forceinline__ void cpa16(uint32_t dst, const float* src) {
    asm volatile("cp.async.cg.shared.global [%0], [%1], 16;\n" :: "r"(dst), "l"(src));
}
__device__ __forceinline__ void cpa_commit() {
    asm volatile("cp.async.commit_group;\n" ::: "memory");
}
__device__ __forceinline__ void cpa_wait2() {
    asm volatile("cp.async.wait_group 2;\n" ::: "memory");
}
__device__ __forceinline__ void ldsm_x4(uint32_t* r, uint32_t addr) {
    asm volatile("ldmatrix.sync.aligned.m8n8.x4.shared.b16 {%0,%1,%2,%3}, [%4];"
                 : "=r"(r[0]), "=r"(r[1]), "=r"(r[2]), "=r"(r[3]) : "r"(addr));
}

__global__ __launch_bounds__(256, 2) void gemm_tf32_kernel(const float* __restrict__ b_h)
{
    extern __shared__ float smem[];
    float* As = smem;                              // STAGES x A_STG_FLT
    float* Bs = smem + STAGES * A_STG_FLT;         // STAGES x B_STG_FLT

    const int tid  = threadIdx.x;
    const int lane = tid & 31;
    const int wid  = tid >> 5;         // 0..7
    const int wm   = wid >> 1;         // 0..3 -> 32 rows
    const int wn   = wid & 1;          // 0..1 -> 64 cols
    const int qid  = lane >> 2;        // 0..7
    const int cid  = lane & 3;         // 0..3
    const int mi   = lane >> 3;        // ldmatrix matrix index 0..3

    const int brow = blockIdx.y * BM;
    const int bcol = blockIdx.x * BN;

    const float* Aops[2] = { g_hr, g_xr };
    const float* Wops[2] = { g_Whp, g_Wxp };

    const uint32_t as_u = (uint32_t)__cvta_generic_to_shared(As);
    const uint32_t bs_u = (uint32_t)__cvta_generic_to_shared(Bs);

    // ldmatrix per-lane offsets (in floats)
    // A: matrix mi -> row += (mi&1)*8, fcol += (mi>>1)*4
    const int a_lane_fl = ((mi & 1) * 8 + (lane & 7)) * ASTR + (mi >> 1) * 4;
    // B: matrix mi -> khalf h = mi&1, n += (mi>>1)*8
    const int b_lane_fl = (mi & 1) * 512 + (wn * 64 + (mi >> 1) * 8 + (lane & 7)) * 4;

    auto stage = [&](int t, int buf) {
        const int pass = t >> 6;
        const int kloc = t & 63;
        const float* A = Aops[pass];
        const float* W = Wops[pass];
        // A: row (tid>>1), half (tid&1)*8 floats, 2 x 16B
        const float* asrc = A + (size_t)(brow + (tid >> 1)) * HID + kloc * 16 + (tid & 1) * 8;
        uint32_t adst = as_u + (uint32_t)(buf * A_STG_FLT + (tid >> 1) * ASTR + (tid & 1) * 8) * 4u;
        cpa16(adst,       asrc);
        cpa16(adst + 16u, asrc + 4);
        // B: chunks cidx = tid*2 + c; q = cidx>>7, n = cidx&127
        #pragma unroll
        for (int cch = 0; cch < 2; ++cch) {
            int cidx = tid * 2 + cch;
            int q = cidx >> 7, n = cidx & 127;
            const float* bsrc = W + ((size_t)(kloc * 4 + q) * NOUT + bcol + n) * 4;
            uint32_t bdst = bs_u + (uint32_t)(buf * B_STG_FLT) * 4u + (uint32_t)cidx * 16u;
            cpa16(bdst, bsrc);
        }
        cpa_commit();
    };

    float acc[2][8][4];
    #pragma unroll
    for (int i = 0; i < 2; ++i)
        #pragma unroll
        for (int j = 0; j < 8; ++j)
            #pragma unroll
            for (int r = 0; r < 4; ++r) acc[i][j][r] = 0.f;

    stage(0, 0); stage(1, 1); stage(2, 2);

    #pragma unroll 1
    for (int t = 0; t < NKTILES; ++t) {
        const int buf = t & (STAGES - 1);
        cpa_wait2();
        __syncthreads();
        if (t + 3 < NKTILES) stage(t + 3, (t + 3) & (STAGES - 1));

        const uint32_t a_base = as_u + (uint32_t)(buf * A_STG_FLT) * 4u;
        const uint32_t b_base = bs_u + (uint32_t)(buf * B_STG_FLT) * 4u;

        #pragma unroll
        for (int g = 0; g < 2; ++g) {
            uint32_t af[2][4];
            #pragma unroll
            for (int i = 0; i < 2; ++i) {
                uint32_t addr = a_base +
                    (uint32_t)((wm * 32 + i * 16) * ASTR + g * 8 + a_lane_fl) * 4u;
                ldsm_x4(af[i], addr);
            }
            uint32_t bf[4][4];
            #pragma unroll
            for (int p = 0; p < 4; ++p) {
                uint32_t addr = b_base +
                    (uint32_t)(g * 1024 + p * 64 + b_lane_fl) * 4u;
                ldsm_x4(bf[p], addr);
            }
            #pragma unroll
            for (int j = 0; j < 8; ++j) {
                uint32_t bx = bf[j >> 1][(j & 1) * 2 + 0];
                uint32_t by = bf[j >> 1][(j & 1) * 2 + 1];
                #pragma unroll
                for (int i = 0; i < 2; ++i) {
                    asm volatile(
                        "mma.sync.aligned.m16n8k8.row.col.f32.tf32.tf32.f32 "
                        "{%0,%1,%2,%3}, {%4,%5,%6,%7}, {%8,%9}, {%0,%1,%2,%3};\n"
                        : "+f"(acc[i][j][0]), "+f"(acc[i][j][1]),
                          "+f"(acc[i][j][2]), "+f"(acc[i][j][3])
                        : "r"(af[i][0]), "r"(af[i][1]), "r"(af[i][2]), "r"(af[i][3]),
                          "r"(bx), "r"(by));
                }
            }
        }
    }

    // Epilogue: bias + store
    #pragma unroll
    for (int i = 0; i < 2; ++i) {
        int r0 = brow + wm * 32 + i * 16 + qid;
        #pragma unroll
        for (int j = 0; j < 8; ++j) {
            int col = bcol + wn * 64 + j * 8 + 2 * cid;
            float2 bb = *(const float2*)&b_h[col];
            float2 v0 = { acc[i][j][0] + bb.x, acc[i][j][1] + bb.y };
            float2 v1 = { acc[i][j][2] + bb.x, acc[i][j][3] + bb.y };
            *(float2*)&g_ifgo[(size_t)r0       * NOUT + col] = v0;
            *(float2*)&g_ifgo[(size_t)(r0 + 8) * NOUT + col] = v1;
        }
    }
}

// ---------------------------------------------------------------------------
// Kernel 2: per-row LayerNorm(4 gates) + LSTM pointwise + LayerNorm(c_next)
// ---------------------------------------------------------------------------
__device__ __forceinline__ void warpReduce2(float& a, float& b) {
    #pragma unroll
    for (int o = 16; o > 0; o >>= 1) {
        a += __shfl_down_sync(0xffffffffu, a, o);
        b += __shfl_down_sync(0xffffffffu, b, o);
    }
}
__device__ __forceinline__ float sigmoidf_(float v) { return 1.0f / (1.0f + expf(-v)); }

__global__ __launch_bounds__(256) void ln_lstm_kernel(
    const float* __restrict__ c,
    const float* __restrict__ ln_g, const float* __restrict__ ln_b,
    const float* __restrict__ lnc_g, const float* __restrict__ lnc_b,
    float* __restrict__ h_next, float* __restrict__ c_next_out)
{
    const int b   = blockIdx.x;
    const int tid = threadIdx.x;
    const int lane = tid & 31, warp = tid >> 5;
    const float* __restrict__ row = &g_ifgo[(size_t)b * NOUT];

    __shared__ float s_wa[8], s_wb[8];
    __shared__ float s_mean[4], s_rstd[4];
    __shared__ float s_c[HID];
    __shared__ float s_o[HID];
    __shared__ float s_cmu, s_crstd;

    #pragma unroll 1
    for (int g = 0; g < 4; ++g) {
        float sum = 0.f, sq = 0.f;
        #pragma unroll
        for (int j = tid; j < HID; j += 256) {
            float v = row[g * HID + j];
            sum += v; sq += v * v;
        }
        warpReduce2(sum, sq);
        if (lane == 0) { s_wa[warp] = sum; s_wb[warp] = sq; }
        __syncthreads();
        if (warp == 0) {
            float a2 = (lane < 8) ? s_wa[lane] : 0.f;
            float b2 = (lane < 8) ? s_wb[lane] : 0.f;
            warpReduce2(a2, b2);
            if (lane == 0) {
                float mu  = a2 * (1.0f / HID);
                float var = b2 * (1.0f / HID) - mu * mu;
                s_mean[g] = mu;
                s_rstd[g] = rsqrtf(var + 1e-5f);
            }
        }
        __syncthreads();
    }

    const float mu_i = s_mean[0], rs_i = s_rstd[0];
    const float mu_f = s_mean[1], rs_f = s_rstd[1];
    const float mu_g = s_mean[2], rs_g = s_rstd[2];
    const float mu_o = s_mean[3], rs_o = s_rstd[3];

    float csum = 0.f, csq = 0.f;
    #pragma unroll
    for (int j = tid; j < HID; j += 256) {
        float iv = (row[0 * HID + j] - mu_i) * rs_i * ln_g[0 * HID + j] + ln_b[0 * HID + j];
        float fv = (row[1 * HID + j] - mu_f) * rs_f * ln_g[1 * HID + j] + ln_b[1 * HID + j];
        float gv = (row[2 * HID + j] - mu_g) * rs_g * ln_g[2 * HID + j] + ln_b[2 * HID + j];
        float ov = (row[3 * HID + j] - mu_o) * rs_o * ln_g[3 * HID + j] + ln_b[3 * HID + j];

        float cn = sigmoidf_(fv) * c[(size_t)b * HID + j] + sigmoidf_(iv) * tanhf(gv);
        s_c[j] = cn;
        s_o[j] = ov;
        c_next_out[(size_t)b * HID + j] = cn;
        csum += cn; csq += cn * cn;
    }

    warpReduce2(csum, csq);
    if (lane == 0) { s_wa[warp] = csum; s_wb[warp] = csq; }
    __syncthreads();
    if (warp == 0) {
        float a2 = (lane < 8) ? s_wa[lane] : 0.f;
        float b2 = (lane < 8) ? s_wb[lane] : 0.f;
        warpReduce2(a2, b2);
        if (lane == 0) {
            float mu  = a2 * (1.0f / HID);
            float var = b2 * (1.0f / HID) - mu * mu;
            s_cmu = mu;
            s_crstd = rsqrtf(var + 1e-5f);
        }
    }
    __syncthreads();

    const float cmu = s_cmu, crstd = s_crstd;
    #pragma unroll
    for (int j = tid; j < HID; j += 256) {
        float lnc = (s_c[j] - cmu) * crstd * lnc_g[j] + lnc_b[j];
        h_next[(size_t)b * HID + j] = sigmoidf_(s_o[j]) * tanhf(lnc);
    }
}

// ---------------------------------------------------------------------------
extern "C" void kernel_launch(void* const* d_in, const int* in_sizes, int n_in,
                              void* d_out, int out_size)
{
    const float* x     = (const float*)d_in[0];
    const float* h     = (const float*)d_in[1];
    const float* c     = (const float*)d_in[2];
    const float* W_h   = (const float*)d_in[3];
    const float* b_h   = (const float*)d_in[4];
    const float* W_x   = (const float*)d_in[5];
    const float* ln_g  = (const float*)d_in[6];
    const float* ln_b  = (const float*)d_in[7];
    const float* lnc_g = (const float*)d_in[8];
    const float* lnc_b = (const float*)d_in[9];

    float* out    = (float*)d_out;
    float* h_next = out;
    float* c_next = out + (size_t)BATCH * HID;

    float *d_hr, *d_xr, *d_Whp, *d_Wxp;
    cudaGetSymbolAddress((void**)&d_hr,  g_hr);
    cudaGetSymbolAddress((void**)&d_xr,  g_xr);
    cudaGetSymbolAddress((void**)&d_Whp, g_Whp);
    cudaGetSymbolAddress((void**)&d_Wxp, g_Wxp);

    cvt_hx_kernel<<<1024, 256>>>(h, d_hr, x, d_xr, BATCH * HID);
    dim3 pgrid(NOUT / 256, HID / 4);
    pack_w_kernel<<<pgrid, 256>>>(W_h, d_Whp);
    pack_w_kernel<<<pgrid, 256>>>(W_x, d_Wxp);

    cudaFuncSetAttribute(gemm_tf32_kernel,
                         cudaFuncAttributeMaxDynamicSharedMemorySize, GEMM_SMEM);
    dim3 grid(NOUT / BN, BATCH / BM);
    gemm_tf32_kernel<<<grid, 256, GEMM_SMEM>>>(b_h);

    ln_lstm_kernel<<<BATCH, 256>>>(c, ln_g, ln_b, lnc_g, lnc_b, h_next, c_next);
}

// round 7
// speedup vs baseline: 1.7250x; 1.0502x over previous
#include <cuda_runtime.h>
#include <math.h>
#include <stdint.h>

#define BATCH 4096
#define HID   1024
#define NOUT  4096   // 4*H

// Scratch (graph-capture safe static device globals)
__device__ float g_ifgo[(size_t)BATCH * NOUT];
__device__ float g_hr [(size_t)BATCH * HID];    // tf32-rounded, row-major
__device__ float g_xr [(size_t)BATCH * HID];
__device__ float g_Whp[(size_t)HID * NOUT];     // packed [k/4][n][4] tf32
__device__ float g_Wxp[(size_t)HID * NOUT];

// ---------------------------------------------------------------------------
// Prepass 1: h/x -> tf32(RNA), plain row-major.
// ---------------------------------------------------------------------------
__global__ void cvt_hx_kernel(const float* __restrict__ s0, float* __restrict__ d0,
                              const float* __restrict__ s1, float* __restrict__ d1, int n)
{
    int stride = gridDim.x * blockDim.x;
    for (int i = blockIdx.x * blockDim.x + threadIdx.x; i < n; i += stride) {
        uint32_t u;
        asm("cvt.rna.tf32.f32 %0, %1;" : "=r"(u) : "f"(s0[i])); d0[i] = __uint_as_float(u);
        asm("cvt.rna.tf32.f32 %0, %1;" : "=r"(u) : "f"(s1[i])); d1[i] = __uint_as_float(u);
    }
}

// ---------------------------------------------------------------------------
// Prepass 2: W [1024 k][4096 n] -> Wp [k/4][n][k%4], tf32(RNA). Both weights.
// ---------------------------------------------------------------------------
__global__ __launch_bounds__(256) void pack_w_kernel(
    const float* __restrict__ W0, float* __restrict__ Wp0,
    const float* __restrict__ W1, float* __restrict__ Wp1)
{
    const int n  = blockIdx.x * 256 + threadIdx.x;
    const int k4 = blockIdx.y;
    const float* W  = (blockIdx.z == 0) ? W0  : W1;
    float*       Wp = (blockIdx.z == 0) ? Wp0 : Wp1;
    float4 v;
    uint32_t u;
    asm("cvt.rna.tf32.f32 %0, %1;" : "=r"(u) : "f"(W[(size_t)(k4 * 4 + 0) * NOUT + n])); v.x = __uint_as_float(u);
    asm("cvt.rna.tf32.f32 %0, %1;" : "=r"(u) : "f"(W[(size_t)(k4 * 4 + 1) * NOUT + n])); v.y = __uint_as_float(u);
    asm("cvt.rna.tf32.f32 %0, %1;" : "=r"(u) : "f"(W[(size_t)(k4 * 4 + 2) * NOUT + n])); v.z = __uint_as_float(u);
    asm("cvt.rna.tf32.f32 %0, %1;" : "=r"(u) : "f"(W[(size_t)(k4 * 4 + 3) * NOUT + n])); v.w = __uint_as_float(u);
    *(float4*)&Wp[((size_t)k4 * NOUT + n) * 4] = v;
}

// ---------------------------------------------------------------------------
// tf32 mma.sync GEMM: ifgo = h @ W_h + x @ W_x + b_h
// CTA 128x128, 8 warps (4x2 of 32x64), BK=16, 4-stage cp.async ring,
// all 12 ldmatrix issued up-front per tile, then 32 back-to-back MMAs.
// ---------------------------------------------------------------------------
#define BM 128
#define BN 128
#define BK 16
#define ASTR 20                    // A smem row stride (floats)
#define STAGES 4
#define NKTILES 128                // 2 passes * (1024/16)
#define A_STG_FLT (BM * ASTR)      // 2560 floats = 10240 B
#define B_STG_FLT (BK * BN)        // 2048 floats =  8192 B
#define GEMM_SMEM ((A_STG_FLT + B_STG_FLT) * STAGES * 4)   // 73728 B

__device__ __forceinline__ void cpa16(uint32_t dst, const float* src) {
    asm volatile("cp.async.cg.shared.global [%0], [%1], 16;\n" :: "r"(dst), "l"(src));
}
__device__ __forceinline__ void cpa_commit() {
    asm volatile("cp.async.commit_group;\n" ::: "memory");
}
__device__ __forceinline__ void cpa_wait2() {
    asm volatile("cp.async.wait_group 2;\n" ::: "memory");
}
__device__ __forceinline__ void ldsm_x4(uint32_t* r, uint32_t addr) {
    asm volatile("ldmatrix.sync.aligned.m8n8.x4.shared.b16 {%0,%1,%2,%3}, [%4];"
                 : "=r"(r[0]), "=r"(r[1]), "=r"(r[2]), "=r"(r[3]) : "r"(addr));
}

__global__ __launch_bounds__(256, 2) void gemm_tf32_kernel(const float* __restrict__ b_h)
{
    extern __shared__ float smem[];
    float* As = smem;                              // STAGES x A_STG_FLT
    float* Bs = smem + STAGES * A_STG_FLT;         // STAGES x B_STG_FLT

    const int tid  = threadIdx.x;
    const int lane = tid & 31;
    const int wid  = tid >> 5;         // 0..7
    const int wm   = wid >> 1;         // 0..3 -> 32 rows
    const int wn   = wid & 1;          // 0..1 -> 64 cols
    const int qid  = lane >> 2;        // 0..7
    const int cid  = lane & 3;         // 0..3
    const int mi   = lane >> 3;        // ldmatrix matrix index 0..3

    const int brow = blockIdx.y * BM;
    const int bcol = blockIdx.x * BN;

    const float* Aops[2] = { g_hr, g_xr };
    const float* Wops[2] = { g_Whp, g_Wxp };

    const uint32_t as_u = (uint32_t)__cvta_generic_to_shared(As);
    const uint32_t bs_u = (uint32_t)__cvta_generic_to_shared(Bs);

    // ldmatrix per-lane offsets (in floats) — identical math to round 6
    const int a_lane_fl = ((mi & 1) * 8 + (lane & 7)) * ASTR + (mi >> 1) * 4;
    const int b_lane_fl = (mi & 1) * 512 + (wn * 64 + (mi >> 1) * 8 + (lane & 7)) * 4;

    // warp-level ldmatrix base addresses (add buf offset per tile)
    const uint32_t a_warp_u = as_u + (uint32_t)(wm * 32 * ASTR + a_lane_fl) * 4u;
    const uint32_t b_warp_u = bs_u + (uint32_t)(b_lane_fl) * 4u;

    auto stage = [&](int t, int buf) {
        const int pass = t >> 6;
        const int kloc = t & 63;
        const float* A = Aops[pass];
        const float* W = Wops[pass];
        const float* asrc = A + (size_t)(brow + (tid >> 1)) * HID + kloc * 16 + (tid & 1) * 8;
        uint32_t adst = as_u + (uint32_t)(buf * A_STG_FLT + (tid >> 1) * ASTR + (tid & 1) * 8) * 4u;
        cpa16(adst,       asrc);
        cpa16(adst + 16u, asrc + 4);
        #pragma unroll
        for (int cch = 0; cch < 2; ++cch) {
            int cidx = tid * 2 + cch;
            int q = cidx >> 7, n = cidx & 127;
            const float* bsrc = W + ((size_t)(kloc * 4 + q) * NOUT + bcol + n) * 4;
            uint32_t bdst = bs_u + (uint32_t)(buf * B_STG_FLT) * 4u + (uint32_t)cidx * 16u;
            cpa16(bdst, bsrc);
        }
        cpa_commit();
    };

    float acc[2][8][4];
    #pragma unroll
    for (int i = 0; i < 2; ++i)
        #pragma unroll
        for (int j = 0; j < 8; ++j)
            #pragma unroll
            for (int r = 0; r < 4; ++r) acc[i][j][r] = 0.f;

    stage(0, 0); stage(1, 1); stage(2, 2);

    #pragma unroll 1
    for (int t = 0; t < NKTILES; ++t) {
        const int buf = t & (STAGES - 1);
        cpa_wait2();
        __syncthreads();
        if (t + 3 < NKTILES) stage(t + 3, (t + 3) & (STAGES - 1));

        const uint32_t a_base = a_warp_u + (uint32_t)(buf * A_STG_FLT) * 4u;
        const uint32_t b_base = b_warp_u + (uint32_t)(buf * B_STG_FLT) * 4u;

        // ---- all 12 ldmatrix up-front (A g0,g1 then B g0 then B g1) ----
        uint32_t af[2][2][4];   // [g][i][4]
        uint32_t bf[2][4][4];   // [g][p][4]
        #pragma unroll
        for (int g = 0; g < 2; ++g)
            #pragma unroll
            for (int i = 0; i < 2; ++i)
                ldsm_x4(af[g][i], a_base + (uint32_t)(i * 16 * ASTR + g * 8) * 4u);
        #pragma unroll
        for (int g = 0; g < 2; ++g)
            #pragma unroll
            for (int p = 0; p < 4; ++p)
                ldsm_x4(bf[g][p], b_base + (uint32_t)(g * 1024 + p * 64) * 4u);

        // ---- 32 MMAs ----
        #pragma unroll
        for (int g = 0; g < 2; ++g) {
            #pragma unroll
            for (int j = 0; j < 8; ++j) {
                uint32_t bx = bf[g][j >> 1][(j & 1) * 2 + 0];
                uint32_t by = bf[g][j >> 1][(j & 1) * 2 + 1];
                #pragma unroll
                for (int i = 0; i < 2; ++i) {
                    asm volatile(
                        "mma.sync.aligned.m16n8k8.row.col.f32.tf32.tf32.f32 "
                        "{%0,%1,%2,%3}, {%4,%5,%6,%7}, {%8,%9}, {%0,%1,%2,%3};\n"
                        : "+f"(acc[i][j][0]), "+f"(acc[i][j][1]),
                          "+f"(acc[i][j][2]), "+f"(acc[i][j][3])
                        : "r"(af[g][i][0]), "r"(af[g][i][1]),
                          "r"(af[g][i][2]), "r"(af[g][i][3]),
                          "r"(bx), "r"(by));
                }
            }
        }
    }

    // Epilogue: bias + store
    #pragma unroll
    for (int i = 0; i < 2; ++i) {
        int r0 = brow + wm * 32 + i * 16 + qid;
        #pragma unroll
        for (int j = 0; j < 8; ++j) {
            int col = bcol + wn * 64 + j * 8 + 2 * cid;
            float2 bb = *(const float2*)&b_h[col];
            float2 v0 = { acc[i][j][0] + bb.x, acc[i][j][1] + bb.y };
            float2 v1 = { acc[i][j][2] + bb.x, acc[i][j][3] + bb.y };
            *(float2*)&g_ifgo[(size_t)r0       * NOUT + col] = v0;
            *(float2*)&g_ifgo[(size_t)(r0 + 8) * NOUT + col] = v1;
        }
    }
}

// ---------------------------------------------------------------------------
// Kernel 2: per-row LayerNorm(4 gates) + LSTM pointwise + LayerNorm(c_next)
// One block (256 threads) per row; each thread owns one float4 per gate.
// ---------------------------------------------------------------------------
__device__ __forceinline__ float sigmoidf_(float v) { return 1.0f / (1.0f + expf(-v)); }

__global__ __launch_bounds__(256) void ln_lstm_kernel(
    const float* __restrict__ c,
    const float* __restrict__ ln_g, const float* __restrict__ ln_b,
    const float* __restrict__ lnc_g, const float* __restrict__ lnc_b,
    float* __restrict__ h_next, float* __restrict__ c_next_out)
{
    const int b    = blockIdx.x;
    const int tid  = threadIdx.x;
    const int lane = tid & 31, warp = tid >> 5;
    const float* __restrict__ row = &g_ifgo[(size_t)b * NOUT];
    const int j4 = tid * 4;   // this thread's 4 columns

    __shared__ float s_st[8][8];   // [warp][stat]
    __shared__ float s_stats[8];   // mu_i..o, rs_i..o interleaved: [g]=mu, [g+4]=rs... see below
    __shared__ float s_c2[8][2];
    __shared__ float s_cstat[2];

    // ---- load all four gate float4s ----
    float4 vi = *(const float4*)&row[0 * HID + j4];
    float4 vf = *(const float4*)&row[1 * HID + j4];
    float4 vg = *(const float4*)&row[2 * HID + j4];
    float4 vo = *(const float4*)&row[3 * HID + j4];

    // ---- 8 stats: sum/sq per gate ----
    float st[8];
    st[0] = vi.x + vi.y + vi.z + vi.w;
    st[1] = vf.x + vf.y + vf.z + vf.w;
    st[2] = vg.x + vg.y + vg.z + vg.w;
    st[3] = vo.x + vo.y + vo.z + vo.w;
    st[4] = vi.x*vi.x + vi.y*vi.y + vi.z*vi.z + vi.w*vi.w;
    st[5] = vf.x*vf.x + vf.y*vf.y + vf.z*vf.z + vf.w*vf.w;
    st[6] = vg.x*vg.x + vg.y*vg.y + vg.z*vg.z + vg.w*vg.w;
    st[7] = vo.x*vo.x + vo.y*vo.y + vo.z*vo.z + vo.w*vo.w;
    #pragma unroll
    for (int o = 16; o > 0; o >>= 1)
        #pragma unroll
        for (int s = 0; s < 8; ++s)
            st[s] += __shfl_down_sync(0xffffffffu, st[s], o);
    if (lane == 0)
        #pragma unroll
        for (int s = 0; s < 8; ++s) s_st[warp][s] = st[s];
    __syncthreads();
    if (warp == 0) {
        // lane l: stat = l&7, source warps (l>>3) and (l>>3)+4
        float v = s_st[lane >> 3][lane & 7] + s_st[(lane >> 3) + 4][lane & 7];
        v += __shfl_down_sync(0xffffffffu, v, 16);
        v += __shfl_down_sync(0xffffffffu, v, 8);
        if (lane < 8) {
            if (lane < 4) {
                s_stats[lane] = v * (1.0f / HID);              // mean of gate 'lane'
            } else {
                // placeholder; rstd computed below after means known
                s_st[0][lane] = v * (1.0f / HID);              // E[x^2]
            }
        }
    }
    __syncthreads();
    if (warp == 0 && lane < 4) {
        float mu = s_stats[lane];
        float ex2 = s_st[0][lane + 4];
        s_stats[lane + 4] = rsqrtf(ex2 - mu * mu + 1e-5f);
    }
    __syncthreads();

    const float mu_i = s_stats[0], mu_f = s_stats[1], mu_g = s_stats[2], mu_o = s_stats[3];
    const float rs_i = s_stats[4], rs_f = s_stats[5], rs_g = s_stats[6], rs_o = s_stats[7];

    // ---- LN + LSTM pointwise (registers only) ----
    float4 gi = *(const float4*)&ln_g[0 * HID + j4];
    float4 gf = *(const float4*)&ln_g[1 * HID + j4];
    float4 gg = *(const float4*)&ln_g[2 * HID + j4];
    float4 go = *(const float4*)&ln_g[3 * HID + j4];
    float4 bi = *(const float4*)&ln_b[0 * HID + j4];
    float4 bff = *(const float4*)&ln_b[1 * HID + j4];
    float4 bg = *(const float4*)&ln_b[2 * HID + j4];
    float4 bo = *(const float4*)&ln_b[3 * HID + j4];
    float4 cv = *(const float4*)&c[(size_t)b * HID + j4];

    float cn[4], ov[4];
    float csum = 0.f, csq = 0.f;
    {
        const float* pvi = &vi.x; const float* pvf = &vf.x;
        const float* pvg = &vg.x; const float* pvo = &vo.x;
        const float* pgi = &gi.x; const float* pgf = &gf.x;
        const float* pgg = &gg.x; const float* pgo = &go.x;
        const float* pbi = &bi.x; const float* pbf = &bff.x;
        const float* pbg = &bg.x; const float* pbo = &bo.x;
        const float* pc  = &cv.x;
        #pragma unroll
        for (int e = 0; e < 4; ++e) {
            float ivv = (pvi[e] - mu_i) * rs_i * pgi[e] + pbi[e];
            float fvv = (pvf[e] - mu_f) * rs_f * pgf[e] + pbf[e];
            float gvv = (pvg[e] - mu_g) * rs_g * pgg[e] + pbg[e];
            ov[e]     = (pvo[e] - mu_o) * rs_o * pgo[e] + pbo[e];
            cn[e] = sigmoidf_(fvv) * pc[e] + sigmoidf_(ivv) * tanhf(gvv);
            csum += cn[e]; csq += cn[e] * cn[e];
        }
    }
    *(float4*)&c_next_out[(size_t)b * HID + j4] = *(float4*)cn;

    // ---- c_next stats ----
    #pragma unroll
    for (int o = 16; o > 0; o >>= 1) {
        csum += __shfl_down_sync(0xffffffffu, csum, o);
        csq  += __shfl_down_sync(0xffffffffu, csq,  o);
    }
    if (lane == 0) { s_c2[warp][0] = csum; s_c2[warp][1] = csq; }
    __syncthreads();
    if (warp == 0) {
        float a2 = (lane < 8) ? s_c2[lane][0] : 0.f;
        float b2 = (lane < 8) ? s_c2[lane][1] : 0.f;
        #pragma unroll
        for (int o = 4; o > 0; o >>= 1) {
            a2 += __shfl_down_sync(0xffffffffu, a2, o);
            b2 += __shfl_down_sync(0xffffffffu, b2, o);
        }
        if (lane == 0) {
            float mu  = a2 * (1.0f / HID);
            float var = b2 * (1.0f / HID) - mu * mu;
            s_cstat[0] = mu;
            s_cstat[1] = rsqrtf(var + 1e-5f);
        }
    }
    __syncthreads();

    const float cmu = s_cstat[0], crstd = s_cstat[1];
    float4 lg = *(const float4*)&lnc_g[j4];
    float4 lb = *(const float4*)&lnc_b[j4];
    float hn[4];
    {
        const float* plg = &lg.x; const float* plb = &lb.x;
        #pragma unroll
        for (int e = 0; e < 4; ++e) {
            float lnc = (cn[e] - cmu) * crstd * plg[e] + plb[e];
            hn[e] = sigmoidf_(ov[e]) * tanhf(lnc);
        }
    }
    *(float4*)&h_next[(size_t)b * HID + j4] = *(float4*)hn;
}

// ---------------------------------------------------------------------------
extern "C" void kernel_launch(void* const* d_in, const int* in_sizes, int n_in,
                              void* d_out, int out_size)
{
    const float* x     = (const float*)d_in[0];
    const float* h     = (const float*)d_in[1];
    const float* c     = (const float*)d_in[2];
    const float* W_h   = (const float*)d_in[3];
    const float* b_h   = (const float*)d_in[4];
    const float* W_x   = (const float*)d_in[5];
    const float* ln_g  = (const float*)d_in[6];
    const float* ln_b  = (const float*)d_in[7];
    const float* lnc_g = (const float*)d_in[8];
    const float* lnc_b = (const float*)d_in[9];

    float* out    = (float*)d_out;
    float* h_next = out;
    float* c_next = out + (size_t)BATCH * HID;

    float *d_hr, *d_xr, *d_Whp, *d_Wxp;
    cudaGetSymbolAddress((void**)&d_hr,  g_hr);
    cudaGetSymbolAddress((void**)&d_xr,  g_xr);
    cudaGetSymbolAddress((void**)&d_Whp, g_Whp);
    cudaGetSymbolAddress((void**)&d_Wxp, g_Wxp);

    cvt_hx_kernel<<<1024, 256>>>(h, d_hr, x, d_xr, BATCH * HID);
    dim3 pgrid(NOUT / 256, HID / 4, 2);
    pack_w_kernel<<<pgrid, 256>>>(W_h, d_Whp, W_x, d_Wxp);

    cudaFuncSetAttribute(gemm_tf32_kernel,
                         cudaFuncAttributeMaxDynamicSharedMemorySize, GEMM_SMEM);
    dim3 grid(NOUT / BN, BATCH / BM);
    gemm_tf32_kernel<<<grid, 256, GEMM_SMEM>>>(b_h);

    ln_lstm_kernel<<<BATCH, 256>>>(c, ln_g, ln_b, lnc_g, lnc_b, h_next, c_next);
}